// round 5
// baseline (speedup 1.0000x reference)
#include <cuda_runtime.h>
#include <math.h>

// ---------------- problem constants (fixed shapes from setup_inputs) -------
#define NB      32          // batch
#define TSAMP   160000      // samples per batch
#define KFFT    1024        // n_fft
#define MWIN    800         // win_length
#define HOP     600
#define NBINS   256
#define NF      267         // 1 + (160000+1024-1024)/600
#define NFP     134         // frame pairs (two real frames per complex FFT)
#define LMAXW   13
#define LMINW   3
#define FT      (NBINS*NF)  // 68352 (worst-case valid keys per batch)
#define TWN     768         // twiddle table: exp(-2pi i k/1024), k<768
#define SEG     32          // median hist segments per batch

// ---------------- scratch (__device__ globals, no allocation) --------------
__device__ float        g_win[MWIN];
__device__ float2       g_tw[TWN];
__device__ float        g_Yt[NB*NF*NBINS];      // [B, T, F] (stft-coalesced)
__device__ float        g_Y [NB*NBINS*NF];      // [B, F, T] (rt60-coalesced)
__device__ unsigned int g_keys[NB*FT];          // compacted valid keys
__device__ int          g_nvalid[NB];
__device__ int          g_hist[NB][256];
__device__ unsigned int g_pfx[NB];
__device__ int          g_k[NB];
__device__ int          g_done[4];

// ---------------- init: tables (double precision) + state reset ------------
__global__ __launch_bounds__(256) void init_kernel() {
    int gid = blockIdx.x * 256 + threadIdx.x;     // grid 8x256 -> 2048
    if (gid < MWIN) {
        double v = 0.5 - 0.5 * cos(2.0 * M_PI * (double)gid / (double)MWIN);
        g_win[gid] = (float)v;
    }
    int tj = gid - MWIN;
    if (tj >= 0 && tj < TWN) {
        double a = -2.0 * M_PI * (double)tj / (double)KFFT;
        g_tw[tj] = make_float2((float)cos(a), (float)sin(a));
    }
    if (gid < NB) g_nvalid[gid] = 0;
    if (gid < 4)  g_done[gid] = 0;
    for (int j = gid; j < NB * 256; j += 2048) ((int*)g_hist)[j] = 0;
}

// ---------------- STFT power: one block per (batch, frame-pair) ------------
// Two real frames packed as re/im of one complex 1024-pt FFT (radix-4
// Stockham autosort, 5 iterations), unpacked via Hermitian symmetry.
// Output layout [B, T, F] so the 256 bin writes per frame are coalesced.
__global__ __launch_bounds__(256) void stft_kernel(const float* __restrict__ y) {
    const int p  = blockIdx.x % NFP;
    const int b  = blockIdx.x / NFP;
    const int fa = 2 * p;
    const int fb = 2 * p + 1;                    // may be NF (dropped)
    __shared__ float  Are[KFFT], Aim[KFFT], Bre[KFFT], Bim[KFFT];
    __shared__ float2 stw[TWN];
    const int tid = threadIdx.x;

    for (int i = tid; i < TWN; i += 256) stw[i] = g_tw[i];

    const float* yb = y + (size_t)b * TSAMP;
    #pragma unroll
    for (int jj = 0; jj < 4; jj++) {
        int j = tid + jj * 256;
        float va = 0.0f, vb = 0.0f;
        if (j >= 112 && j < 912) {               // zero-padded centered window
            float w = g_win[j - 112];
            int sa = fa * HOP + j - 512;         // center=True: pad K/2 = 512
            if (sa < 0) sa = -sa;
            else if (sa >= TSAMP) sa = 2 * (TSAMP - 1) - sa;
            va = __ldg(yb + sa) * w;
            if (fb < NF) {
                int sb = fb * HOP + j - 512;
                if (sb < 0) sb = -sb;
                else if (sb >= TSAMP) sb = 2 * (TSAMP - 1) - sb;
                vb = __ldg(yb + sb) * w;
            }
        }
        Are[j] = va;                             // natural order (autosort)
        Aim[j] = vb;
    }
    __syncthreads();

    // 5 radix-4 Stockham iterations, Ns = 1,4,16,64,256
    float *sr = Are, *si = Aim, *dr = Bre, *di = Bim;
    #pragma unroll
    for (int it = 0; it < 5; it++) {
        const int Ns = 1 << (2 * it);
        const int m  = tid & (Ns - 1);
        const int ts = 256 >> (2 * it);          // twiddle step = 256/Ns
        float v0r = sr[tid],       v0i = si[tid];
        float v1r = sr[tid + 256], v1i = si[tid + 256];
        float v2r = sr[tid + 512], v2i = si[tid + 512];
        float v3r = sr[tid + 768], v3i = si[tid + 768];
        const int tb = m * ts;
        float2 w1 = stw[tb], w2 = stw[2 * tb], w3 = stw[3 * tb];
        float a1r = w1.x * v1r - w1.y * v1i, a1i = w1.x * v1i + w1.y * v1r;
        float a2r = w2.x * v2r - w2.y * v2i, a2i = w2.x * v2i + w2.y * v2r;
        float a3r = w3.x * v3r - w3.y * v3i, a3i = w3.x * v3i + w3.y * v3r;
        float t0r = v0r + a2r, t0i = v0i + a2i;
        float t1r = v0r - a2r, t1i = v0i - a2i;
        float t2r = a1r + a3r, t2i = a1i + a3i;
        float t3r = a1r - a3r, t3i = a1i - a3i;
        if (it == 0) {                            // contiguous: float4 store
            ((float4*)dr)[tid] = make_float4(t0r + t2r, t1r + t3i,
                                             t0r - t2r, t1r - t3i);
            ((float4*)di)[tid] = make_float4(t0i + t2i, t1i - t3r,
                                             t0i - t2i, t1i + t3r);
        } else {
            const int idxD = ((tid >> (2 * it)) << (2 * it + 2)) + m;
            dr[idxD]          = t0r + t2r; di[idxD]          = t0i + t2i;
            dr[idxD + Ns]     = t1r + t3i; di[idxD + Ns]     = t1i - t3r;
            dr[idxD + 2 * Ns] = t0r - t2r; di[idxD + 2 * Ns] = t0i - t2i;
            dr[idxD + 3 * Ns] = t1r - t3i; di[idxD + 3 * Ns] = t1i + t3r;
        }
        __syncthreads();
        float* tp;
        tp = sr; sr = dr; dr = tp;
        tp = si; si = di; di = tp;
    }

    // unpack two real spectra from one complex FFT; power; [B, T, F] layout
    const int k  = tid;
    const int km = (KFFT - k) & (KFFT - 1);
    float ar = sr[k],  ai = si[k];
    float br = sr[km], bi = -si[km];             // conj(Z[K-k])
    float xar = 0.5f * (ar + br), xai = 0.5f * (ai + bi);
    float ddr = ar - br,          ddi = ai - bi;
    float xbr = 0.5f * ddi,       xbi = -0.5f * ddr;
    g_Yt[((size_t)b * NF + fa) * NBINS + k] = xar * xar + xai * xai;
    if (fb < NF)
        g_Yt[((size_t)b * NF + fb) * NBINS + k] = xbr * xbr + xbi * xbi;
}

// ---------------- transpose [B,T,F] -> [B,F,T] (32x32 tiles) ----------------
__global__ __launch_bounds__(256) void transpose_kernel() {
    __shared__ float tile[32][33];
    const int b  = blockIdx.z;
    const int f0 = blockIdx.x * 32;              // 8 tiles cover F=256
    const int t0 = blockIdx.y * 32;              // 9 tiles cover T=267
    const int tx = threadIdx.x, ty = threadIdx.y;  // 32 x 8

    #pragma unroll
    for (int r = 0; r < 4; r++) {
        int t = t0 + ty + r * 8;
        if (t < NF)
            tile[ty + r * 8][tx] = g_Yt[((size_t)b * NF + t) * NBINS + f0 + tx];
    }
    __syncthreads();
    #pragma unroll
    for (int r = 0; r < 4; r++) {
        int t = t0 + tx;
        int f = f0 + ty + r * 8;
        if (t < NF)
            g_Y[((size_t)b * NBINS + f) * NF + t] = tile[tx][ty + r * 8];
    }
}

// ---------------- RT60 per (batch, subband): compact valid keys -------------
__global__ __launch_bounds__(128) void rt60_kernel() {
    const int f = blockIdx.x % NBINS;
    const int b = blockIdx.x / NBINS;
    __shared__ float         sy[NF];
    __shared__ unsigned char sdl[NF];
    __shared__ unsigned int  skey[NF];
    __shared__ int           sbest;
    __shared__ int           scnt;
    __shared__ int           sbase;
    const int tid = threadIdx.x;
    if (tid == 0) { sbest = 0; scnt = 0; }

    const float* row = g_Y + ((size_t)b * NBINS + f) * NF;
    for (int t = tid; t < NF; t += 128) sy[t] = row[t];
    __syncthreads();

    // run length of strict decreases starting at t (capped at LMAX-1)
    int localbest = 0;
    for (int t = tid; t < NF; t += 128) {
        int c = 0;
        while (c < LMAXW - 1 && t + c + 1 < NF && sy[t + c + 1] < sy[t + c]) c++;
        sdl[t] = (unsigned char)c;
        int cand = c + 1;
        int rem  = NF - t;
        if (cand > rem)   cand = rem;
        if (cand > LMAXW) cand = LMAXW;
        if (cand > localbest) localbest = cand;
    }
    atomicMax(&sbest, localbest);
    __syncthreads();

    const int lenL = sbest;
    if (lenL < LMINW) return;                    // no decreasing window at all

    const float xm  = 0.5f * (float)(lenL - 1);
    const float den = (float)lenL * (float)(lenL * lenL - 1) / 12.0f;

    for (int t = tid; t < NF; t += 128) {
        if (t + lenL <= NF && (int)sdl[t] >= lenL - 1) {
            // EDC: reverse cumsum in same order as reference, then dB
            float acc = 0.0f;
            float db[LMAXW];
            for (int j = lenL - 1; j >= 0; j--) {
                acc += sy[t + j];
                db[j] = 10.0f * log10f(fmaxf(acc, 1e-10f));
            }
            float d0 = db[0];
            if (db[lenL - 1] - d0 < -10.0f) {    // selected
                float num = 0.0f;
                for (int j = 1; j < lenL; j++)
                    num += ((float)j - xm) * (db[j] - d0);
                float slope = num / den;         // slope <= 0 here
                float rt60  = (-60.0f / slope) * 0.0375f;  // HOP/FS
                unsigned int u = __float_as_uint(rt60);
                unsigned int key = (u & 0x80000000u) ? ~u : (u | 0x80000000u);
                int pos = atomicAdd(&scnt, 1);   // smem atomic (cheap)
                skey[pos] = key;
            }
        }
    }
    __syncthreads();

    const int cnt = scnt;
    if (cnt == 0) return;
    if (tid == 0) sbase = atomicAdd(&g_nvalid[b], cnt);  // ONE global atomic
    __syncthreads();
    unsigned int* dst = g_keys + (size_t)b * FT + sbase;
    for (int i = tid; i < cnt; i += 128) dst[i] = skey[i];
}

// ---------------- median: 4 radix passes, multi-block + last-block select ---
__global__ __launch_bounds__(256) void pass_kernel(int pass,
                                                   const float* __restrict__ coeffs,
                                                   float* __restrict__ out) {
    const int b   = blockIdx.x >> 5;             // SEG = 32
    const int seg = blockIdx.x & (SEG - 1);
    const int tid = threadIdx.x;
    __shared__ int h[256];
    __shared__ int slast;

    h[tid] = 0;
    __syncthreads();

    const int n = g_nvalid[b];
    const int shift = 24 - 8 * pass;
    const unsigned int pfx   = (pass == 0) ? 0u : g_pfx[b];
    const unsigned int hmask = (pass == 0) ? 0u : (0xFFFFFFFFu << (shift + 8));
    const int chunk = (n + SEG - 1) / SEG;
    const int start = seg * chunk;
    const int end   = (start + chunk < n) ? start + chunk : n;
    const unsigned int* keys = g_keys + (size_t)b * FT;
    for (int i = start + tid; i < end; i += 256) {
        unsigned int key = keys[i];
        if ((key & hmask) == pfx) atomicAdd(&h[(key >> shift) & 255], 1);
    }
    __syncthreads();
    if (h[tid]) atomicAdd(&g_hist[b][tid], h[tid]);
    __syncthreads();

    if (tid == 0) {
        __threadfence();
        int t = atomicAdd(&g_done[pass], 1);
        slast = (t == (int)gridDim.x - 1);
    }
    __syncthreads();
    if (!slast) return;
    __threadfence();

    // ---- last block: select for all 32 batches (one warp per 4 batches) ----
    const int w = tid >> 5, lane = tid & 31;
    for (int b2 = w; b2 < NB; b2 += 8) {
        const int n2 = g_nvalid[b2];
        if (n2 == 0) {
            if (pass == 3 && lane == 0) out[b2] = 0.5f;  // DEFAULT_RT60
            continue;
        }
        const int base = lane * 8;
        int c[8]; int s = 0;
        #pragma unroll
        for (int q = 0; q < 8; q++) { c[q] = g_hist[b2][base + q]; s += c[q]; }
        int excl = s;
        #pragma unroll
        for (int off = 1; off < 32; off <<= 1) {
            int nn = __shfl_up_sync(0xFFFFFFFFu, excl, off);
            if (lane >= off) excl += nn;
        }
        excl -= s;                                // exclusive prefix across lanes
        int k0 = (pass == 0) ? ((n2 - 1) >> 1) : g_k[b2];
        int bin = 256, cumAt = 0, cum = excl;
        #pragma unroll
        for (int q = 0; q < 8; q++) {
            if (bin == 256 && cum + c[q] > k0) { bin = base + q; cumAt = cum; }
            cum += c[q];
        }
        unsigned int ball = __ballot_sync(0xFFFFFFFFu, bin < 256);
        int src = __ffs(ball) - 1;                // guaranteed: total >= k0+1
        if (lane == src) {
            g_k[b2] = k0 - cumAt;
            unsigned int npfx = ((pass == 0) ? 0u : g_pfx[b2])
                              | ((unsigned int)bin << shift);
            g_pfx[b2] = npfx;
            if (pass == 3) {
                unsigned int u = (npfx & 0x80000000u) ? (npfx ^ 0x80000000u)
                                                      : ~npfx;
                float med = __uint_as_float(u);
                out[b2] = fmaxf(coeffs[0] + coeffs[1] * med, 0.01f);
            }
        }
        // reset this batch's histogram for the next pass / next replay
        #pragma unroll
        for (int q = 0; q < 8; q++) g_hist[b2][base + q] = 0;
    }
    __syncthreads();
    if (tid == 0) g_done[pass] = 0;               // reset for next replay
}

// ---------------- launcher ---------------------------------------------------
extern "C" void kernel_launch(void* const* d_in, const int* in_sizes, int n_in,
                              void* d_out, int out_size) {
    const float* y      = (const float*)d_in[0];
    const float* coeffs = (const float*)d_in[1];
    float*       out    = (float*)d_out;

    init_kernel<<<8, 256>>>();
    stft_kernel<<<NB * NFP, 256>>>(y);
    dim3 tgrid(8, 9, NB), tblk(32, 8);
    transpose_kernel<<<tgrid, tblk>>>();
    rt60_kernel<<<NB * NBINS, 128>>>();
    for (int pass = 0; pass < 4; pass++)
        pass_kernel<<<NB * SEG, 256>>>(pass, coeffs, out);
}

// round 6
// speedup vs baseline: 1.5918x; 1.5918x over previous
#include <cuda_runtime.h>
#include <math.h>

// ---------------- problem constants (fixed shapes from setup_inputs) -------
#define NB      32          // batch
#define TSAMP   160000      // samples per batch
#define KFFT    1024        // n_fft
#define MWIN    800         // win_length
#define HOP     600
#define NBINS   256
#define NF      267         // 1 + (160000+1024-1024)/600
#define NFP     134         // frame pairs (two real frames per complex FFT)
#define LMAXW   13
#define LMINW   3
#define FT      (NBINS*NF)  // 68352 (worst-case valid keys per batch)
#define TWN     768         // twiddle table: exp(-2pi i k/1024), k<768
#define SMEMK   8192        // median smem key cache capacity

// ---------------- scratch (__device__ globals, no allocation) --------------
__device__ float        g_Y[NB*NBINS*NF];       // [B, F, T]
__device__ unsigned int g_keys[NB*FT];          // compacted valid keys
__device__ int          g_nvalid[NB];

// ---------------- STFT power: one block per (batch, frame-pair) ------------
// Two real frames packed as re/im of one complex 1024-pt FFT (radix-4
// Stockham autosort), unpacked via Hermitian symmetry. Tables built per
// block via sincospif/cospif (~1 ulp, same accuracy as a double table).
__global__ __launch_bounds__(256) void stft_kernel(const float* __restrict__ y) {
    const int p  = blockIdx.x % NFP;
    const int b  = blockIdx.x / NFP;
    const int fa = 2 * p;
    const int fb = 2 * p + 1;                    // may be NF (dropped)
    __shared__ float  Are[KFFT], Aim[KFFT], Bre[KFFT], Bim[KFFT];
    __shared__ float2 stw[TWN];
    const int tid = threadIdx.x;

    if (p == 0 && tid == 0) g_nvalid[b] = 0;     // replay-state reset

    #pragma unroll
    for (int i = tid; i < TWN; i += 256) {       // exp(-2*pi*i*k/1024)
        float s, c;
        sincospif(-(float)i / 512.0f, &s, &c);
        stw[i] = make_float2(c, s);
    }

    const float* yb = y + (size_t)b * TSAMP;
    #pragma unroll
    for (int jj = 0; jj < 4; jj++) {
        int j = tid + jj * 256;
        float va = 0.0f, vb = 0.0f;
        if (j >= 112 && j < 912) {               // zero-padded centered window
            // periodic hann: 0.5 - 0.5*cos(2*pi*n/800)
            float w = 0.5f - 0.5f * cospif((float)(j - 112) / 400.0f);
            int sa = fa * HOP + j - 512;         // center=True: pad K/2 = 512
            if (sa < 0) sa = -sa;
            else if (sa >= TSAMP) sa = 2 * (TSAMP - 1) - sa;
            va = __ldg(yb + sa) * w;
            if (fb < NF) {
                int sb = fb * HOP + j - 512;
                if (sb < 0) sb = -sb;
                else if (sb >= TSAMP) sb = 2 * (TSAMP - 1) - sb;
                vb = __ldg(yb + sb) * w;
            }
        }
        Are[j] = va;                             // natural order (autosort)
        Aim[j] = vb;
    }
    __syncthreads();

    // radix-4 Stockham, iterations Ns = 1,4,16,64 then a trimmed Ns=256
    float *sr = Are, *si = Aim, *dr = Bre, *di = Bim;
    #pragma unroll
    for (int it = 0; it < 4; it++) {
        const int Ns = 1 << (2 * it);
        const int m  = tid & (Ns - 1);
        const int ts = 256 >> (2 * it);          // twiddle step = 256/Ns
        float v0r = sr[tid],       v0i = si[tid];
        float v1r = sr[tid + 256], v1i = si[tid + 256];
        float v2r = sr[tid + 512], v2i = si[tid + 512];
        float v3r = sr[tid + 768], v3i = si[tid + 768];
        const int tb = m * ts;
        float2 w1 = stw[tb], w2 = stw[2 * tb], w3 = stw[3 * tb];
        float a1r = w1.x * v1r - w1.y * v1i, a1i = w1.x * v1i + w1.y * v1r;
        float a2r = w2.x * v2r - w2.y * v2i, a2i = w2.x * v2i + w2.y * v2r;
        float a3r = w3.x * v3r - w3.y * v3i, a3i = w3.x * v3i + w3.y * v3r;
        float t0r = v0r + a2r, t0i = v0i + a2i;
        float t1r = v0r - a2r, t1i = v0i - a2i;
        float t2r = a1r + a3r, t2i = a1i + a3i;
        float t3r = a1r - a3r, t3i = a1i - a3i;
        if (it == 0) {                            // contiguous: float4 store
            ((float4*)dr)[tid] = make_float4(t0r + t2r, t1r + t3i,
                                             t0r - t2r, t1r - t3i);
            ((float4*)di)[tid] = make_float4(t0i + t2i, t1i - t3r,
                                             t0i - t2i, t1i + t3r);
        } else {
            const int idxD = ((tid >> (2 * it)) << (2 * it + 2)) + m;
            dr[idxD]          = t0r + t2r; di[idxD]          = t0i + t2i;
            dr[idxD + Ns]     = t1r + t3i; di[idxD + Ns]     = t1i - t3r;
            dr[idxD + 2 * Ns] = t0r - t2r; di[idxD + 2 * Ns] = t0i - t2i;
            dr[idxD + 3 * Ns] = t1r - t3i; di[idxD + 3 * Ns] = t1i + t3r;
        }
        __syncthreads();
        float* tp;
        tp = sr; sr = dr; dr = tp;
        tp = si; si = di; di = tp;
    }

    // final stage (Ns=256): only outputs [0,255] and [769,1023] are needed
    {
        float v0r = sr[tid],       v0i = si[tid];
        float v1r = sr[tid + 256], v1i = si[tid + 256];
        float v2r = sr[tid + 512], v2i = si[tid + 512];
        float v3r = sr[tid + 768], v3i = si[tid + 768];
        float2 w1 = stw[tid], w2 = stw[2 * tid], w3 = stw[3 * tid];
        float a1r = w1.x * v1r - w1.y * v1i, a1i = w1.x * v1i + w1.y * v1r;
        float a2r = w2.x * v2r - w2.y * v2i, a2i = w2.x * v2i + w2.y * v2r;
        float a3r = w3.x * v3r - w3.y * v3i, a3i = w3.x * v3i + w3.y * v3r;
        float t0r = v0r + a2r, t0i = v0i + a2i;
        float t1r = v0r - a2r, t1i = v0i - a2i;
        float t2r = a1r + a3r, t2i = a1i + a3i;
        float t3r = a1r - a3r, t3i = a1i - a3i;
        dr[tid]       = t0r + t2r; di[tid]       = t0i + t2i;  // Z[tid]
        dr[tid + 768] = t1r - t3i; di[tid + 768] = t1i + t3r;  // Z[tid+768]
        __syncthreads();
        float* tp;
        tp = sr; sr = dr; dr = tp;
        tp = si; si = di; di = tp;
    }

    // unpack two real spectra from one complex FFT; power, layout [B, F, T]
    const int k  = tid;
    const int km = (KFFT - k) & (KFFT - 1);
    float ar = sr[k],  ai = si[k];
    float br = sr[km], bi = -si[km];             // conj(Z[K-k])
    float xar = 0.5f * (ar + br), xai = 0.5f * (ai + bi);
    float ddr = ar - br,          ddi = ai - bi;
    float xbr = 0.5f * ddi,       xbi = -0.5f * ddr;
    float* Yrow = g_Y + ((size_t)b * NBINS + k) * NF;
    Yrow[fa] = xar * xar + xai * xai;
    if (fb < NF) Yrow[fb] = xbr * xbr + xbi * xbi;
}

// ---------------- RT60 per (batch, subband): compact valid keys -------------
__global__ __launch_bounds__(128) void rt60_kernel() {
    const int f = blockIdx.x % NBINS;
    const int b = blockIdx.x / NBINS;
    __shared__ float         sy[NF];
    __shared__ unsigned char sd[NF];             // strict-decrease flags
    __shared__ unsigned char sdl[NF];            // run length from t
    __shared__ unsigned int  skey[NF];
    __shared__ int           sbest;
    __shared__ int           scnt;
    __shared__ int           sbase;
    const int tid = threadIdx.x;
    if (tid == 0) { sbest = 0; scnt = 0; }

    const float* row = g_Y + ((size_t)b * NBINS + f) * NF;
    for (int t = tid; t < NF; t += 128) sy[t] = row[t];
    __syncthreads();
    for (int t = tid; t < NF; t += 128)
        sd[t] = (t + 1 < NF) ? (sy[t + 1] < sy[t]) : 0;
    __syncthreads();

    // run length of strict decreases starting at t (capped at LMAX-1)
    int localbest = 0;
    for (int t = tid; t < NF; t += 128) {
        int c = 0;
        while (c < LMAXW - 1 && t + c < NF && sd[t + c]) c++;
        sdl[t] = (unsigned char)c;
        int cand = c + 1;
        int rem  = NF - t;
        if (cand > rem)   cand = rem;
        if (cand > LMAXW) cand = LMAXW;
        if (cand > localbest) localbest = cand;
    }
    atomicMax(&sbest, localbest);
    __syncthreads();

    const int lenL = sbest;
    if (lenL < LMINW) return;                    // no decreasing window at all

    const float xm  = 0.5f * (float)(lenL - 1);
    const float den = (float)lenL * (float)(lenL * lenL - 1) / 12.0f;

    for (int t = tid; t < NF; t += 128) {
        if (t + lenL <= NF && (int)sdl[t] >= lenL - 1) {
            // EDC: reverse cumsum in same order as reference, then dB
            float acc = 0.0f;
            float db[LMAXW];
            for (int j = lenL - 1; j >= 0; j--) {
                acc += sy[t + j];
                db[j] = 10.0f * log10f(fmaxf(acc, 1e-10f));
            }
            float d0 = db[0];
            if (db[lenL - 1] - d0 < -10.0f) {    // selected
                float num = 0.0f;
                for (int j = 1; j < lenL; j++)
                    num += ((float)j - xm) * (db[j] - d0);
                float slope = num / den;         // slope <= 0 here
                float rt60  = (-60.0f / slope) * 0.0375f;  // HOP/FS
                unsigned int u = __float_as_uint(rt60);
                unsigned int key = (u & 0x80000000u) ? ~u : (u | 0x80000000u);
                int pos = atomicAdd(&scnt, 1);   // smem atomic (cheap)
                skey[pos] = key;
            }
        }
    }
    __syncthreads();

    const int cnt = scnt;
    if (cnt == 0) return;
    if (tid == 0) sbase = atomicAdd(&g_nvalid[b], cnt);  // ONE global atomic
    __syncthreads();
    unsigned int* dst = g_keys + (size_t)b * FT + sbase;
    for (int i = tid; i < cnt; i += 128) dst[i] = skey[i];
}

// ---------------- median: one block per batch, 4-pass radix select ----------
__global__ __launch_bounds__(512) void median_kernel(const float* __restrict__ coeffs,
                                                     float* __restrict__ out) {
    const int b   = blockIdx.x;
    const int tid = threadIdx.x;
    __shared__ unsigned int skeys[SMEMK];
    __shared__ int          hist[256];
    __shared__ unsigned int s_pfx;
    __shared__ int          s_k;

    const int n = g_nvalid[b];
    if (n == 0) {
        if (tid == 0) out[b] = 0.5f;             // DEFAULT_RT60 (>= 0.01)
        return;
    }
    const unsigned int* gk = g_keys + (size_t)b * FT;
    const bool fits = (n <= SMEMK);
    if (fits)
        for (int i = tid; i < n; i += 512) skeys[i] = gk[i];
    if (tid == 0) { s_pfx = 0u; s_k = (n - 1) >> 1; }
    __syncthreads();

    #pragma unroll
    for (int pass = 0; pass < 4; pass++) {
        for (int i = tid; i < 256; i += 512) hist[i] = 0;
        __syncthreads();
        const int shift = 24 - 8 * pass;
        const unsigned int pfx   = s_pfx;
        const unsigned int hmask = (pass == 0) ? 0u : (0xFFFFFFFFu << (shift + 8));
        if (fits) {
            for (int i = tid; i < n; i += 512) {
                unsigned int key = skeys[i];
                if ((key & hmask) == pfx) atomicAdd(&hist[(key >> shift) & 255], 1);
            }
        } else {
            for (int i = tid; i < n; i += 512) {
                unsigned int key = gk[i];
                if ((key & hmask) == pfx) atomicAdd(&hist[(key >> shift) & 255], 1);
            }
        }
        __syncthreads();

        if (tid < 32) {                          // warp-scan bin select
            const int lane = tid;
            const int base = lane * 8;
            int c[8]; int s = 0;
            #pragma unroll
            for (int q = 0; q < 8; q++) { c[q] = hist[base + q]; s += c[q]; }
            int excl = s;
            #pragma unroll
            for (int off = 1; off < 32; off <<= 1) {
                int nn = __shfl_up_sync(0xFFFFFFFFu, excl, off);
                if (lane >= off) excl += nn;
            }
            excl -= s;                           // exclusive prefix across lanes
            const int k0 = s_k;
            int bin = 256, cumAt = 0, cum = excl;
            #pragma unroll
            for (int q = 0; q < 8; q++) {
                if (bin == 256 && cum + c[q] > k0) { bin = base + q; cumAt = cum; }
                cum += c[q];
            }
            unsigned int ball = __ballot_sync(0xFFFFFFFFu, bin < 256);
            int src = __ffs(ball) - 1;           // guaranteed: total >= k0+1
            if (lane == src) {
                s_k   = k0 - cumAt;
                s_pfx = pfx | ((unsigned int)bin << shift);
            }
        }
        __syncthreads();
    }

    if (tid == 0) {
        unsigned int key = s_pfx;
        unsigned int u = (key & 0x80000000u) ? (key ^ 0x80000000u) : ~key;
        float med = __uint_as_float(u);
        out[b] = fmaxf(coeffs[0] + coeffs[1] * med, 0.01f);
    }
}

// ---------------- launcher ---------------------------------------------------
extern "C" void kernel_launch(void* const* d_in, const int* in_sizes, int n_in,
                              void* d_out, int out_size) {
    const float* y      = (const float*)d_in[0];
    const float* coeffs = (const float*)d_in[1];
    float*       out    = (float*)d_out;

    stft_kernel<<<NB * NFP, 256>>>(y);
    rt60_kernel<<<NB * NBINS, 128>>>();
    median_kernel<<<NB, 512>>>(coeffs, out);
}

// round 7
// speedup vs baseline: 1.6486x; 1.0357x over previous
#include <cuda_runtime.h>
#include <math.h>

// ---------------- problem constants (fixed shapes from setup_inputs) -------
#define NB      32          // batch
#define TSAMP   160000      // samples per batch
#define KFFT    1024        // n_fft
#define MWIN    800         // win_length
#define HOP     600
#define NBINS   256
#define NF      267         // 1 + (160000+1024-1024)/600
#define NFP     134         // frame pairs (two real frames per complex FFT)
#define LMAXW   13
#define LMINW   3
#define FT      (NBINS*NF)  // 68352 (worst-case valid keys per batch)
#define TWN     768         // twiddle table: exp(-2pi i k/1024), k<768
#define SMEMK   8192        // median smem key cache capacity

// skewed smem layouts (conflict-free Stockham stores/loads)
#define PHIA(a) ((a) + 4 * ((a) >> 5))    // buffer A layout (stage1 -> stage2)
#define PHIB(a) ((a) + 16 * ((a) >> 6))   // buffer B layout (stage2 -> stage3)
#define SZA     1152                      // 1023 + 4*31 = 1147 < 1152
#define SZB     1280                      // 1023 + 16*15 = 1263 < 1280

// ---------------- scratch (__device__ globals, no allocation) --------------
__device__ float        g_Y[NB*NBINS*NF];       // [B, F, T]
__device__ unsigned int g_keys[NB*FT];          // compacted valid keys
__device__ int          g_nvalid[NB];

// ---------------- STFT power: one block per (batch, frame-pair) ------------
// Two real frames packed as re/im of one complex 1024-pt FFT (radix-4
// Stockham autosort), unpacked via Hermitian symmetry. Skewed shared-memory
// layouts make every stage's loads AND stores bank-conflict-free.
__global__ __launch_bounds__(256) void stft_kernel(const float* __restrict__ y) {
    const int p  = blockIdx.x % NFP;
    const int b  = blockIdx.x / NFP;
    const int fa = 2 * p;
    const int fb = 2 * p + 1;                    // may be NF (dropped)
    __shared__ float  Are[SZA], Aim[SZA], Bre[SZB], Bim[SZB];
    __shared__ float2 stw[TWN];
    const int tid = threadIdx.x;

    if (p == 0 && tid == 0) g_nvalid[b] = 0;     // replay-state reset

    for (int i = tid; i < TWN; i += 256) {       // exp(-2*pi*i*k/1024)
        float s, c;
        sincospif(-(float)i / 512.0f, &s, &c);
        stw[i] = make_float2(c, s);
    }

    const float* yb = y + (size_t)b * TSAMP;
    #pragma unroll
    for (int jj = 0; jj < 4; jj++) {
        int j = tid + jj * 256;
        float va = 0.0f, vb = 0.0f;
        if (j >= 112 && j < 912) {               // zero-padded centered window
            // periodic hann: 0.5 - 0.5*cos(2*pi*n/800)
            float w = 0.5f - 0.5f * cospif((float)(j - 112) / 400.0f);
            int sa = fa * HOP + j - 512;         // center=True: pad K/2 = 512
            if (sa < 0) sa = -sa;
            else if (sa >= TSAMP) sa = 2 * (TSAMP - 1) - sa;
            va = __ldg(yb + sa) * w;
            if (fb < NF) {
                int sb = fb * HOP + j - 512;
                if (sb < 0) sb = -sb;
                else if (sb >= TSAMP) sb = 2 * (TSAMP - 1) - sb;
                vb = __ldg(yb + sb) * w;
            }
        }
        Are[j] = va;                             // natural order (autosort)
        Aim[j] = vb;
    }
    __syncthreads();

    // radix-4 Stockham, Ns = 1,4,16,64 (+ trimmed Ns=256 below)
    // ping-pong: A(id) ->0-> B(id) ->1-> A(PHIA) ->2-> B(PHIB) ->3-> A(id) ->4-> B(id)
    float *sr = Are, *si = Aim, *dr = Bre, *di = Bim;
    #pragma unroll
    for (int it = 0; it < 4; it++) {
        const int Ns = 1 << (2 * it);
        const int m  = tid & (Ns - 1);
        const int ts = 256 >> (2 * it);          // twiddle step = 256/Ns
        int i0 = tid, i1 = tid + 256, i2 = tid + 512, i3 = tid + 768;
        if (it == 2) { i0 = PHIA(i0); i1 = PHIA(i1); i2 = PHIA(i2); i3 = PHIA(i3); }
        if (it == 3) { i0 = PHIB(i0); i1 = PHIB(i1); i2 = PHIB(i2); i3 = PHIB(i3); }
        float v0r = sr[i0], v0i = si[i0];
        float v1r = sr[i1], v1i = si[i1];
        float v2r = sr[i2], v2i = si[i2];
        float v3r = sr[i3], v3i = si[i3];
        const int tb = m * ts;
        float2 w1 = stw[tb], w2 = stw[2 * tb], w3 = stw[3 * tb];
        float a1r = w1.x * v1r - w1.y * v1i, a1i = w1.x * v1i + w1.y * v1r;
        float a2r = w2.x * v2r - w2.y * v2i, a2i = w2.x * v2i + w2.y * v2r;
        float a3r = w3.x * v3r - w3.y * v3i, a3i = w3.x * v3i + w3.y * v3r;
        float t0r = v0r + a2r, t0i = v0i + a2i;
        float t1r = v0r - a2r, t1i = v0i - a2i;
        float t2r = a1r + a3r, t2i = a1i + a3i;
        float t3r = a1r - a3r, t3i = a1i - a3i;
        if (it == 0) {                            // contiguous: float4 store
            ((float4*)dr)[tid] = make_float4(t0r + t2r, t1r + t3i,
                                             t0r - t2r, t1r - t3i);
            ((float4*)di)[tid] = make_float4(t0i + t2i, t1i - t3r,
                                             t0i - t2i, t1i + t3r);
        } else {
            const int idxD = ((tid >> (2 * it)) << (2 * it + 2)) + m;
            int o0 = idxD, o1 = idxD + Ns, o2 = idxD + 2 * Ns, o3 = idxD + 3 * Ns;
            if (it == 1) { o0 = PHIA(o0); o1 = PHIA(o1); o2 = PHIA(o2); o3 = PHIA(o3); }
            if (it == 2) { o0 = PHIB(o0); o1 = PHIB(o1); o2 = PHIB(o2); o3 = PHIB(o3); }
            dr[o0] = t0r + t2r; di[o0] = t0i + t2i;
            dr[o1] = t1r + t3i; di[o1] = t1i - t3r;
            dr[o2] = t0r - t2r; di[o2] = t0i - t2i;
            dr[o3] = t1r - t3i; di[o3] = t1i + t3r;
        }
        __syncthreads();
        float* tp;
        tp = sr; sr = dr; dr = tp;
        tp = si; si = di; di = tp;
    }

    // final stage (Ns=256): only outputs [0,255] and [769,1023] are needed
    {
        float v0r = sr[tid],       v0i = si[tid];
        float v1r = sr[tid + 256], v1i = si[tid + 256];
        float v2r = sr[tid + 512], v2i = si[tid + 512];
        float v3r = sr[tid + 768], v3i = si[tid + 768];
        float2 w1 = stw[tid], w2 = stw[2 * tid], w3 = stw[3 * tid];
        float a1r = w1.x * v1r - w1.y * v1i, a1i = w1.x * v1i + w1.y * v1r;
        float a2r = w2.x * v2r - w2.y * v2i, a2i = w2.x * v2i + w2.y * v2r;
        float a3r = w3.x * v3r - w3.y * v3i, a3i = w3.x * v3i + w3.y * v3r;
        float t0r = v0r + a2r, t0i = v0i + a2i;
        float t1r = v0r - a2r, t1i = v0i - a2i;
        float t2r = a1r + a3r, t2i = a1i + a3i;
        float t3r = a1r - a3r, t3i = a1i - a3i;
        dr[tid]       = t0r + t2r; di[tid]       = t0i + t2i;  // Z[tid]
        dr[tid + 768] = t1r - t3i; di[tid + 768] = t1i + t3r;  // Z[tid+768]
        __syncthreads();
        float* tp;
        tp = sr; sr = dr; dr = tp;
        tp = si; si = di; di = tp;
    }

    // unpack two real spectra from one complex FFT; power, layout [B, F, T]
    const int k  = tid;
    const int km = (KFFT - k) & (KFFT - 1);
    float ar = sr[k],  ai = si[k];
    float br = sr[km], bi = -si[km];             // conj(Z[K-k])
    float xar = 0.5f * (ar + br), xai = 0.5f * (ai + bi);
    float ddr = ar - br,          ddi = ai - bi;
    float xbr = 0.5f * ddi,       xbi = -0.5f * ddr;
    float* Yrow = g_Y + ((size_t)b * NBINS + k) * NF;
    Yrow[fa] = xar * xar + xai * xai;
    if (fb < NF) Yrow[fb] = xbr * xbr + xbi * xbi;
}

// ---------------- RT60 per (batch, subband): compact valid keys -------------
__global__ __launch_bounds__(128) void rt60_kernel() {
    const int f = blockIdx.x % NBINS;
    const int b = blockIdx.x / NBINS;
    __shared__ float         sy[NF];
    __shared__ unsigned char sd[NF];             // strict-decrease flags
    __shared__ unsigned char sdl[NF];            // run length from t
    __shared__ unsigned int  skey[NF];
    __shared__ int           sbest;
    __shared__ int           scnt;
    __shared__ int           sbase;
    const int tid = threadIdx.x;
    if (tid == 0) { sbest = 0; scnt = 0; }

    const float* row = g_Y + ((size_t)b * NBINS + f) * NF;
    for (int t = tid; t < NF; t += 128) sy[t] = row[t];
    __syncthreads();
    for (int t = tid; t < NF; t += 128)
        sd[t] = (t + 1 < NF) ? (sy[t + 1] < sy[t]) : 0;
    __syncthreads();

    // run length of strict decreases starting at t (capped at LMAX-1)
    int localbest = 0;
    for (int t = tid; t < NF; t += 128) {
        int c = 0;
        while (c < LMAXW - 1 && t + c < NF && sd[t + c]) c++;
        sdl[t] = (unsigned char)c;
        int cand = c + 1;
        int rem  = NF - t;
        if (cand > rem)   cand = rem;
        if (cand > LMAXW) cand = LMAXW;
        if (cand > localbest) localbest = cand;
    }
    atomicMax(&sbest, localbest);
    __syncthreads();

    const int lenL = sbest;
    if (lenL < LMINW) return;                    // no decreasing window at all

    const float xm  = 0.5f * (float)(lenL - 1);
    const float den = (float)lenL * (float)(lenL * lenL - 1) / 12.0f;

    for (int t = tid; t < NF; t += 128) {
        if (t + lenL <= NF && (int)sdl[t] >= lenL - 1) {
            // EDC: reverse cumsum in same order as reference, then dB
            float acc = 0.0f;
            float db[LMAXW];
            for (int j = lenL - 1; j >= 0; j--) {
                acc += sy[t + j];
                db[j] = 10.0f * log10f(fmaxf(acc, 1e-10f));
            }
            float d0 = db[0];
            if (db[lenL - 1] - d0 < -10.0f) {    // selected
                float num = 0.0f;
                for (int j = 1; j < lenL; j++)
                    num += ((float)j - xm) * (db[j] - d0);
                float slope = num / den;         // slope <= 0 here
                float rt60  = (-60.0f / slope) * 0.0375f;  // HOP/FS
                unsigned int u = __float_as_uint(rt60);
                unsigned int key = (u & 0x80000000u) ? ~u : (u | 0x80000000u);
                int pos = atomicAdd(&scnt, 1);   // smem atomic (cheap)
                skey[pos] = key;
            }
        }
    }
    __syncthreads();

    const int cnt = scnt;
    if (cnt == 0) return;
    if (tid == 0) sbase = atomicAdd(&g_nvalid[b], cnt);  // ONE global atomic
    __syncthreads();
    unsigned int* dst = g_keys + (size_t)b * FT + sbase;
    for (int i = tid; i < cnt; i += 128) dst[i] = skey[i];
}

// ---------------- median: one block per batch, 4-pass radix select ----------
__global__ __launch_bounds__(512) void median_kernel(const float* __restrict__ coeffs,
                                                     float* __restrict__ out) {
    const int b   = blockIdx.x;
    const int tid = threadIdx.x;
    __shared__ unsigned int skeys[SMEMK];
    __shared__ int          hist[256];
    __shared__ unsigned int s_pfx;
    __shared__ int          s_k;

    const int n = g_nvalid[b];
    if (n == 0) {
        if (tid == 0) out[b] = 0.5f;             // DEFAULT_RT60 (>= 0.01)
        return;
    }
    const unsigned int* gk = g_keys + (size_t)b * FT;
    const bool fits = (n <= SMEMK);
    if (fits)
        for (int i = tid; i < n; i += 512) skeys[i] = gk[i];
    if (tid == 0) { s_pfx = 0u; s_k = (n - 1) >> 1; }
    __syncthreads();

    #pragma unroll
    for (int pass = 0; pass < 4; pass++) {
        for (int i = tid; i < 256; i += 512) hist[i] = 0;
        __syncthreads();
        const int shift = 24 - 8 * pass;
        const unsigned int pfx   = s_pfx;
        const unsigned int hmask = (pass == 0) ? 0u : (0xFFFFFFFFu << (shift + 8));
        if (fits) {
            for (int i = tid; i < n; i += 512) {
                unsigned int key = skeys[i];
                if ((key & hmask) == pfx) atomicAdd(&hist[(key >> shift) & 255], 1);
            }
        } else {
            for (int i = tid; i < n; i += 512) {
                unsigned int key = gk[i];
                if ((key & hmask) == pfx) atomicAdd(&hist[(key >> shift) & 255], 1);
            }
        }
        __syncthreads();

        if (tid < 32) {                          // warp-scan bin select
            const int lane = tid;
            const int base = lane * 8;
            int c[8]; int s = 0;
            #pragma unroll
            for (int q = 0; q < 8; q++) { c[q] = hist[base + q]; s += c[q]; }
            int excl = s;
            #pragma unroll
            for (int off = 1; off < 32; off <<= 1) {
                int nn = __shfl_up_sync(0xFFFFFFFFu, excl, off);
                if (lane >= off) excl += nn;
            }
            excl -= s;                           // exclusive prefix across lanes
            const int k0 = s_k;
            int bin = 256, cumAt = 0, cum = excl;
            #pragma unroll
            for (int q = 0; q < 8; q++) {
                if (bin == 256 && cum + c[q] > k0) { bin = base + q; cumAt = cum; }
                cum += c[q];
            }
            unsigned int ball = __ballot_sync(0xFFFFFFFFu, bin < 256);
            int src = __ffs(ball) - 1;           // guaranteed: total >= k0+1
            if (lane == src) {
                s_k   = k0 - cumAt;
                s_pfx = pfx | ((unsigned int)bin << shift);
            }
        }
        __syncthreads();
    }

    if (tid == 0) {
        unsigned int key = s_pfx;
        unsigned int u = (key & 0x80000000u) ? (key ^ 0x80000000u) : ~key;
        float med = __uint_as_float(u);
        out[b] = fmaxf(coeffs[0] + coeffs[1] * med, 0.01f);
    }
}

// ---------------- launcher ---------------------------------------------------
extern "C" void kernel_launch(void* const* d_in, const int* in_sizes, int n_in,
                              void* d_out, int out_size) {
    const float* y      = (const float*)d_in[0];
    const float* coeffs = (const float*)d_in[1];
    float*       out    = (float*)d_out;

    stft_kernel<<<NB * NFP, 256>>>(y);
    rt60_kernel<<<NB * NBINS, 128>>>();
    median_kernel<<<NB, 512>>>(coeffs, out);
}

// round 8
// speedup vs baseline: 2.2225x; 1.3481x over previous
#include <cuda_runtime.h>
#include <math.h>

// ---------------- problem constants (fixed shapes from setup_inputs) -------
#define NB      32          // batch
#define TSAMP   160000      // samples per batch
#define KFFT    1024        // n_fft
#define MWIN    800         // win_length
#define HOP     600
#define NBINS   256
#define NF      267         // 1 + (160000+1024-1024)/600
#define NFP     134         // frame pairs (two real frames per complex FFT)
#define LMAXW   13
#define LMINW   3
#define FT      (NBINS*NF)  // 68352 (worst-case valid keys per batch)
#define SMEMK   8192        // median smem key cache capacity

#define PHI1(a) ((a) + 4 * ((a) >> 4))   // skew for stage1->stage2 buffer
#define TWI(i)  ((i) + ((i) >> 4))       // skewed twiddle index (CF strided reads)

__device__ __forceinline__ float2 cmul(float2 a, float2 b) {
    return make_float2(a.x * b.x - a.y * b.y, a.x * b.y + a.y * b.x);
}

// ---------------- scratch (__device__ globals, no allocation) --------------
__device__ float        g_Y[NB*NBINS*NF];       // [B, F, T]
__device__ unsigned int g_keys[NB*FT];          // compacted valid keys
__device__ int          g_nvalid[NB];

// ---------------- STFT power: one block per (batch, frame-pair) ------------
// Two real frames packed as re/im of one complex 1024-pt FFT (radix-4
// Stockham autosort, float2 interleaved smem, 1 twiddle load per stage,
// trimmed final stage), unpacked via Hermitian symmetry.
__global__ __launch_bounds__(256) void stft_kernel(const float* __restrict__ y) {
    const int p  = blockIdx.x % NFP;
    const int b  = blockIdx.x / NFP;
    const int fa = 2 * p;
    const int fb = 2 * p + 1;                    // may be NF (dropped)
    __shared__ __align__(16) float2 A[1280];
    __shared__ __align__(16) float2 B[1024];
    __shared__ float2 stw[272];
    const int tid = threadIdx.x;

    if (p == 0 && tid == 0) g_nvalid[b] = 0;     // replay-state reset

    {   // twiddle table: exp(-2*pi*i*k/1024), k<256, skew-stored
        float s, c;
        sincospif(-(float)tid / 512.0f, &s, &c);
        stw[TWI(tid)] = make_float2(c, s);
    }

    const float* yb = y + (size_t)b * TSAMP;
    #pragma unroll
    for (int jj = 0; jj < 4; jj++) {
        int j = tid + jj * 256;
        float va = 0.0f, vb = 0.0f;
        if (j >= 112 && j < 912) {               // zero-padded centered window
            float w = 0.5f - 0.5f * cospif((float)(j - 112) / 400.0f);
            int sa = fa * HOP + j - 512;         // center=True: pad K/2 = 512
            if (sa < 0) sa = -sa;
            else if (sa >= TSAMP) sa = 2 * (TSAMP - 1) - sa;
            va = __ldg(yb + sa) * w;
            if (fb < NF) {
                int sb = fb * HOP + j - 512;
                if (sb < 0) sb = -sb;
                else if (sb >= TSAMP) sb = 2 * (TSAMP - 1) - sb;
                vb = __ldg(yb + sb) * w;
            }
        }
        A[j] = make_float2(va, vb);              // natural order (autosort)
    }
    __syncthreads();

    // stage 0 (Ns=1, twiddles = 1): A -> B, outputs contiguous -> STS.128 x2
    {
        float2 v0 = A[tid], v1 = A[tid + 256], v2 = A[tid + 512], v3 = A[tid + 768];
        float2 t0 = {v0.x + v2.x, v0.y + v2.y}, t1 = {v0.x - v2.x, v0.y - v2.y};
        float2 t2 = {v1.x + v3.x, v1.y + v3.y}, t3 = {v1.x - v3.x, v1.y - v3.y};
        ((float4*)B)[2 * tid]     = make_float4(t0.x + t2.x, t0.y + t2.y,
                                                t1.x + t3.y, t1.y - t3.x);
        ((float4*)B)[2 * tid + 1] = make_float4(t0.x - t2.x, t0.y - t2.y,
                                                t1.x - t3.y, t1.y + t3.x);
    }
    __syncthreads();

    #define BFLY(w1, v0, v1, v2, v3, o0, o1, o2, o3)                          \
        {                                                                     \
            float2 w2 = cmul(w1, w1), w3 = cmul(w1, w2);                      \
            float2 a1 = cmul(w1, v1), a2 = cmul(w2, v2), a3 = cmul(w3, v3);   \
            float2 t0 = {v0.x + a2.x, v0.y + a2.y};                           \
            float2 t1 = {v0.x - a2.x, v0.y - a2.y};                           \
            float2 t2 = {a1.x + a3.x, a1.y + a3.y};                           \
            float2 t3 = {a1.x - a3.x, a1.y - a3.y};                           \
            o0 = make_float2(t0.x + t2.x, t0.y + t2.y);                       \
            o1 = make_float2(t1.x + t3.y, t1.y - t3.x);                       \
            o2 = make_float2(t0.x - t2.x, t0.y - t2.y);                       \
            o3 = make_float2(t1.x - t3.y, t1.y + t3.x);                       \
        }

    // stage 1 (Ns=4): B -> A (PHI1 layout)
    {
        const int m = tid & 3;
        float2 v0 = B[tid], v1 = B[tid + 256], v2 = B[tid + 512], v3 = B[tid + 768];
        float2 w1 = stw[TWI(m * 64)];
        float2 o0, o1, o2, o3;
        BFLY(w1, v0, v1, v2, v3, o0, o1, o2, o3);
        const int base = ((tid >> 2) << 4) + m;
        A[PHI1(base)]      = o0; A[PHI1(base + 4)]  = o1;
        A[PHI1(base + 8)]  = o2; A[PHI1(base + 12)] = o3;
    }
    __syncthreads();

    // stage 2 (Ns=16): A (PHI1) -> B (identity)
    {
        const int m = tid & 15;
        float2 v0 = A[PHI1(tid)],       v1 = A[PHI1(tid + 256)];
        float2 v2 = A[PHI1(tid + 512)], v3 = A[PHI1(tid + 768)];
        float2 w1 = stw[TWI(m * 16)];
        float2 o0, o1, o2, o3;
        BFLY(w1, v0, v1, v2, v3, o0, o1, o2, o3);
        const int base = ((tid >> 4) << 6) + m;
        B[base]      = o0; B[base + 16] = o1;
        B[base + 32] = o2; B[base + 48] = o3;
    }
    __syncthreads();

    // stage 3 (Ns=64): B -> A (identity)
    {
        const int m = tid & 63;
        float2 v0 = B[tid], v1 = B[tid + 256], v2 = B[tid + 512], v3 = B[tid + 768];
        float2 w1 = stw[TWI(m * 4)];
        float2 o0, o1, o2, o3;
        BFLY(w1, v0, v1, v2, v3, o0, o1, o2, o3);
        const int base = ((tid >> 6) << 8) + m;
        A[base]       = o0; A[base + 64]  = o1;
        A[base + 128] = o2; A[base + 192] = o3;
    }
    __syncthreads();

    // stage 4 (Ns=256, trimmed): Z[tid] stays in regs; only Z[tid+768] -> smem
    float2 zk;
    {
        float2 v0 = A[tid], v1 = A[tid + 256], v2 = A[tid + 512], v3 = A[tid + 768];
        float2 w1 = stw[TWI(tid)];
        float2 w2 = cmul(w1, w1), w3 = cmul(w1, w2);
        float2 a1 = cmul(w1, v1), a2 = cmul(w2, v2), a3 = cmul(w3, v3);
        float2 t0 = {v0.x + a2.x, v0.y + a2.y};
        float2 t1 = {v0.x - a2.x, v0.y - a2.y};
        float2 t2 = {a1.x + a3.x, a1.y + a3.y};
        float2 t3 = {a1.x - a3.x, a1.y - a3.y};
        zk = make_float2(t0.x + t2.x, t0.y + t2.y);          // Z[tid]
        B[768 + tid] = make_float2(t1.x - t3.y, t1.y + t3.x); // Z[tid+768]
    }
    __syncthreads();

    // unpack two real spectra via Hermitian symmetry; power, layout [B, F, T]
    float2 zc = (tid == 0) ? zk : B[1024 - tid];  // Z[K - tid]
    float xar = 0.5f * (zk.x + zc.x), xai = 0.5f * (zk.y - zc.y);
    float ddr = zk.x - zc.x,          ddi = zk.y + zc.y;
    float xbr = 0.5f * ddi,           xbi = -0.5f * ddr;
    float* Yrow = g_Y + ((size_t)b * NBINS + tid) * NF;
    Yrow[fa] = xar * xar + xai * xai;
    if (fb < NF) Yrow[fb] = xbr * xbr + xbi * xbi;
}

// ---------------- RT60 per (batch, subband): compact valid keys -------------
__global__ __launch_bounds__(128) void rt60_kernel() {
    const int f = blockIdx.x % NBINS;
    const int b = blockIdx.x / NBINS;
    __shared__ float        sy[NF];
    __shared__ unsigned int W[12];               // decrease-flag bitmask (267 bits)
    __shared__ unsigned int skey[NF];
    __shared__ int          sbest;
    __shared__ int          scnt;
    __shared__ int          sbase;
    const int tid  = threadIdx.x;
    const int lane = tid & 31;
    if (tid < 12) W[tid] = 0u;
    if (tid == 0) { sbest = 0; scnt = 0; }

    const float* row = g_Y + ((size_t)b * NBINS + f) * NF;
    for (int t = tid; t < NF; t += 128) sy[t] = row[t];
    __syncthreads();

    // pack strict-decrease flags into bitmask words via ballot
    #pragma unroll
    for (int base = 0; base < 288; base += 128) {
        int t = base + tid;
        bool flag = (t + 1 < NF) && (sy[t + 1] < sy[t]);
        unsigned int m = __ballot_sync(0xFFFFFFFFu, flag);
        if (lane == 0 && (t >> 5) < 9) W[t >> 5] = m;
    }
    __syncthreads();

    // best window length: run length from t = ffs of first zero bit
    int localbest = 0;
    for (int t = tid; t < NF; t += 128) {
        int w = t >> 5, r = t & 31;
        unsigned int bits = (W[w] >> r) | (r ? (W[w + 1] << (32 - r)) : 0u);
        unsigned int nb = ~bits;
        int c = nb ? (__ffs(nb) - 1) : 32;
        if (c > LMAXW - 1) c = LMAXW - 1;
        int cand = c + 1;
        int rem  = NF - t;
        if (cand > rem) cand = rem;
        if (cand > localbest) localbest = cand;
    }
    atomicMax(&sbest, localbest);
    __syncthreads();

    const int lenL = sbest;
    if (lenL < LMINW) return;                    // no decreasing window at all

    const float xm  = 0.5f * (float)(lenL - 1);
    const float den = (float)lenL * (float)(lenL * lenL - 1) / 12.0f;

    for (int t = tid; t < NF; t += 128) {
        int w = t >> 5, r = t & 31;
        unsigned int bits = (W[w] >> r) | (r ? (W[w + 1] << (32 - r)) : 0u);
        unsigned int nb = ~bits;
        int c = nb ? (__ffs(nb) - 1) : 32;
        if (t + lenL <= NF && c >= lenL - 1) {
            // EDC: reverse cumsum in same order as reference, then dB
            float acc = 0.0f;
            float db[LMAXW];
            for (int j = lenL - 1; j >= 0; j--) {
                acc += sy[t + j];
                db[j] = 10.0f * log10f(fmaxf(acc, 1e-10f));
            }
            float d0 = db[0];
            if (db[lenL - 1] - d0 < -10.0f) {    // selected
                float num = 0.0f;
                for (int j = 1; j < lenL; j++)
                    num += ((float)j - xm) * (db[j] - d0);
                float slope = num / den;         // slope <= 0 here
                float rt60  = (-60.0f / slope) * 0.0375f;  // HOP/FS
                unsigned int u = __float_as_uint(rt60);
                unsigned int key = (u & 0x80000000u) ? ~u : (u | 0x80000000u);
                int pos = atomicAdd(&scnt, 1);   // smem atomic (cheap)
                skey[pos] = key;
            }
        }
    }
    __syncthreads();

    const int cnt = scnt;
    if (cnt == 0) return;
    if (tid == 0) sbase = atomicAdd(&g_nvalid[b], cnt);  // ONE global atomic
    __syncthreads();
    unsigned int* dst = g_keys + (size_t)b * FT + sbase;
    for (int i = tid; i < cnt; i += 128) dst[i] = skey[i];
}

// ---------------- median: one block per batch, 4-pass radix select ----------
__global__ __launch_bounds__(512) void median_kernel(const float* __restrict__ coeffs,
                                                     float* __restrict__ out) {
    const int b   = blockIdx.x;
    const int tid = threadIdx.x;
    __shared__ unsigned int skeys[SMEMK];
    __shared__ int          hist[256];
    __shared__ unsigned int s_pfx;
    __shared__ int          s_k;

    const int n = g_nvalid[b];
    if (n == 0) {
        if (tid == 0) out[b] = 0.5f;             // DEFAULT_RT60 (>= 0.01)
        return;
    }
    const unsigned int* gk = g_keys + (size_t)b * FT;
    const bool fits = (n <= SMEMK);
    if (fits)
        for (int i = tid; i < n; i += 512) skeys[i] = gk[i];
    if (tid == 0) { s_pfx = 0u; s_k = (n - 1) >> 1; }
    __syncthreads();

    #pragma unroll
    for (int pass = 0; pass < 4; pass++) {
        for (int i = tid; i < 256; i += 512) hist[i] = 0;
        __syncthreads();
        const int shift = 24 - 8 * pass;
        const unsigned int pfx   = s_pfx;
        const unsigned int hmask = (pass == 0) ? 0u : (0xFFFFFFFFu << (shift + 8));
        if (fits) {
            for (int i = tid; i < n; i += 512) {
                unsigned int key = skeys[i];
                if ((key & hmask) == pfx) atomicAdd(&hist[(key >> shift) & 255], 1);
            }
        } else {
            for (int i = tid; i < n; i += 512) {
                unsigned int key = gk[i];
                if ((key & hmask) == pfx) atomicAdd(&hist[(key >> shift) & 255], 1);
            }
        }
        __syncthreads();

        if (tid < 32) {                          // warp-scan bin select
            const int lane = tid;
            const int base = lane * 8;
            int c[8]; int s = 0;
            #pragma unroll
            for (int q = 0; q < 8; q++) { c[q] = hist[base + q]; s += c[q]; }
            int excl = s;
            #pragma unroll
            for (int off = 1; off < 32; off <<= 1) {
                int nn = __shfl_up_sync(0xFFFFFFFFu, excl, off);
                if (lane >= off) excl += nn;
            }
            excl -= s;                           // exclusive prefix across lanes
            const int k0 = s_k;
            int bin = 256, cumAt = 0, cum = excl;
            #pragma unroll
            for (int q = 0; q < 8; q++) {
                if (bin == 256 && cum + c[q] > k0) { bin = base + q; cumAt = cum; }
                cum += c[q];
            }
            unsigned int ball = __ballot_sync(0xFFFFFFFFu, bin < 256);
            int src = __ffs(ball) - 1;           // guaranteed: total >= k0+1
            if (lane == src) {
                s_k   = k0 - cumAt;
                s_pfx = pfx | ((unsigned int)bin << shift);
            }
        }
        __syncthreads();
    }

    if (tid == 0) {
        unsigned int key = s_pfx;
        unsigned int u = (key & 0x80000000u) ? (key ^ 0x80000000u) : ~key;
        float med = __uint_as_float(u);
        out[b] = fmaxf(coeffs[0] + coeffs[1] * med, 0.01f);
    }
}

// ---------------- launcher ---------------------------------------------------
extern "C" void kernel_launch(void* const* d_in, const int* in_sizes, int n_in,
                              void* d_out, int out_size) {
    const float* y      = (const float*)d_in[0];
    const float* coeffs = (const float*)d_in[1];
    float*       out    = (float*)d_out;

    stft_kernel<<<NB * NFP, 256>>>(y);
    rt60_kernel<<<NB * NBINS, 128>>>();
    median_kernel<<<NB, 512>>>(coeffs, out);
}